// round 2
// baseline (speedup 1.0000x reference)
#include <cuda_runtime.h>
#include <math.h>

#define S_LEN 2048
#define BATCH 2
#define EMB   1024
#define NH    16
#define HD    64
#define MTOT  (BATCH * S_LEN)   // 4096

// Scratch (no cudaMalloc allowed): Q, K, V, attention output, each [4096 x 1024] fp32.
__device__ float g_q[MTOT * EMB];
__device__ float g_k[MTOT * EMB];
__device__ float g_v[MTOT * EMB];
__device__ float g_att[MTOT * EMB];

// ---------------------------------------------------------------------------
// SGEMM: C[M,N] = A[M,K] @ B[K,N] (+ bias), all fp32 row-major.
// 64x64 tile, K-tile 32, 256 threads, 4x4 outputs per thread.
// ---------------------------------------------------------------------------
#define TM 64
#define TN 64
#define TK 32

__device__ __forceinline__ void sgemm_body(
    const float* __restrict__ A, const float* __restrict__ B,
    const float* __restrict__ bias, float* __restrict__ C,
    int M, int N, int K)
{
    __shared__ float As[TM][TK + 1];   // padded: conflict-free column reads
    __shared__ float Bs[TK][TN];       // unpadded: float4 row reads

    const int t   = threadIdx.x;
    const int tm0 = blockIdx.y * TM;
    const int tn0 = blockIdx.x * TN;
    const int ty  = t >> 4;            // 0..15
    const int tx  = t & 15;            // 0..15

    float acc[4][4] = {};

    for (int k0 = 0; k0 < K; k0 += TK) {
        // Load A tile (64x32): 2 x float4 per thread
        {
            int row = t >> 3;              // 0..31
            int col = (t & 7) * 4;         // 0..28
            #pragma unroll
            for (int i = 0; i < 2; ++i) {
                float4 v = *(const float4*)&A[(size_t)(tm0 + row + i * 32) * K + k0 + col];
                As[row + i * 32][col + 0] = v.x;
                As[row + i * 32][col + 1] = v.y;
                As[row + i * 32][col + 2] = v.z;
                As[row + i * 32][col + 3] = v.w;
            }
        }
        // Load B tile (32x64): 2 x float4 per thread
        {
            int row = t >> 4;              // 0..15
            int col = (t & 15) * 4;        // 0..60
            #pragma unroll
            for (int i = 0; i < 2; ++i) {
                float4 v = *(const float4*)&B[(size_t)(k0 + row + i * 16) * N + tn0 + col];
                *(float4*)&Bs[row + i * 16][col] = v;
            }
        }
        __syncthreads();

        #pragma unroll
        for (int kk = 0; kk < TK; ++kk) {
            float a0 = As[ty * 4 + 0][kk];
            float a1 = As[ty * 4 + 1][kk];
            float a2 = As[ty * 4 + 2][kk];
            float a3 = As[ty * 4 + 3][kk];
            float4 b4 = *(float4*)&Bs[kk][tx * 4];
            acc[0][0] += a0 * b4.x; acc[0][1] += a0 * b4.y; acc[0][2] += a0 * b4.z; acc[0][3] += a0 * b4.w;
            acc[1][0] += a1 * b4.x; acc[1][1] += a1 * b4.y; acc[1][2] += a1 * b4.z; acc[1][3] += a1 * b4.w;
            acc[2][0] += a2 * b4.x; acc[2][1] += a2 * b4.y; acc[2][2] += a2 * b4.z; acc[2][3] += a2 * b4.w;
            acc[3][0] += a3 * b4.x; acc[3][1] += a3 * b4.y; acc[3][2] += a3 * b4.z; acc[3][3] += a3 * b4.w;
        }
        __syncthreads();
    }

    float bj[4] = {0.f, 0.f, 0.f, 0.f};
    if (bias) {
        #pragma unroll
        for (int j = 0; j < 4; ++j) bj[j] = bias[tn0 + tx * 4 + j];
    }
    #pragma unroll
    for (int i = 0; i < 4; ++i) {
        #pragma unroll
        for (int j = 0; j < 4; ++j) {
            C[(size_t)(tm0 + ty * 4 + i) * N + tn0 + tx * 4 + j] = acc[i][j] + bj[j];
        }
    }
}

__global__ __launch_bounds__(256) void sgemm_kernel(
    const float* __restrict__ A, const float* __restrict__ B,
    const float* __restrict__ bias, float* __restrict__ C,
    int M, int N, int K)
{
    sgemm_body(A, B, bias, C, M, N, K);
}

// Fused QKV projection: blockIdx.z selects {Wq->g_q, Wk->g_k, Wv->g_v}.
__global__ __launch_bounds__(256) void qkv_kernel(
    const float* __restrict__ x,
    const float* __restrict__ Wq, const float* __restrict__ Wk,
    const float* __restrict__ Wv)
{
    const float* W;
    float* C;
    if (blockIdx.z == 0)      { W = Wq; C = g_q; }
    else if (blockIdx.z == 1) { W = Wk; C = g_k; }
    else                      { W = Wv; C = g_v; }
    sgemm_body(x, W, nullptr, C, MTOT, EMB, EMB);
}

// ---------------------------------------------------------------------------
// Flash-attention style causal attention, fp32.
// Block: 64 queries for one (b,h). 256 threads: thread = (row r = t>>2, c = t&3).
// Phase A: each thread computes 16 scores for its row (keys c*16..c*16+15),
//          online softmax over 4-lane groups via shfl.
// Phase B: each thread owns 16 output dims (dims c*16..c*16+15), accumulates
//          P @ V from smem.
// ---------------------------------------------------------------------------
#define PAD 68   // float4-aligned, conflict-free for float4 reads

__global__ __launch_bounds__(256) void attn_kernel()
{
    extern __shared__ float sm[];
    float* Ks = sm;                        // [64][PAD]
    float* Vs = sm + 64 * PAD;             // [64][PAD]
    float* Ps = sm + 2 * 64 * PAD;         // transposed: [k][r] = [64][64]

    const int t  = threadIdx.x;
    const int r  = t >> 2;                 // 0..63 query row
    const int c  = t & 3;                  // 0..3
    const int bq = blockIdx.x;             // query block
    const int h  = blockIdx.y;
    const int b  = blockIdx.z;
    const int qg = bq * 64 + r;            // global query index

    // Load my Q row into registers (float4, redundant x4 across c lanes; cheap)
    const float* qptr = g_q + ((size_t)(b * S_LEN + qg)) * EMB + h * HD;
    float qreg[64];
    #pragma unroll
    for (int d4 = 0; d4 < 16; ++d4) {
        float4 v = ((const float4*)qptr)[d4];
        qreg[d4 * 4 + 0] = v.x; qreg[d4 * 4 + 1] = v.y;
        qreg[d4 * 4 + 2] = v.z; qreg[d4 * 4 + 3] = v.w;
    }

    float O[16] = {};
    float mrow = -1e30f, lrow = 0.f;

    for (int kb = 0; kb <= bq; ++kb) {
        // ---- load K and V tiles (64 x 64 each) ----
        {
            int row0 = t >> 4;             // 0..15
            int col  = (t & 15) * 4;       // 0..60
            #pragma unroll
            for (int i = 0; i < 4; ++i) {
                int row = row0 + i * 16;
                size_t g = ((size_t)(b * S_LEN + kb * 64 + row)) * EMB + h * HD + col;
                *(float4*)&Ks[row * PAD + col] = *(const float4*)&g_k[g];
                *(float4*)&Vs[row * PAD + col] = *(const float4*)&g_v[g];
            }
        }
        __syncthreads();

        // ---- Phase A: scores + online softmax ----
        float p[16];
        float mloc = -1e30f;
        const int kg0 = kb * 64;
        #pragma unroll
        for (int ki = 0; ki < 16; ++ki) {
            int kk = c * 16 + ki;
            const float* kr = &Ks[kk * PAD];
            float s = 0.f;
            #pragma unroll
            for (int d4 = 0; d4 < 16; ++d4) {
                float4 kv = *(const float4*)&kr[d4 * 4];
                s += qreg[d4 * 4 + 0] * kv.x + qreg[d4 * 4 + 1] * kv.y
                   + qreg[d4 * 4 + 2] * kv.z + qreg[d4 * 4 + 3] * kv.w;
            }
            s *= 0.125f;                   // 1/sqrt(64)
            if (kg0 + kk > qg) s = -1e30f; // causal mask
            p[ki] = s;
            mloc = fmaxf(mloc, s);
        }
        mloc = fmaxf(mloc, __shfl_xor_sync(0xffffffffu, mloc, 1));
        mloc = fmaxf(mloc, __shfl_xor_sync(0xffffffffu, mloc, 2));
        float mnew  = fmaxf(mrow, mloc);
        float scale = __expf(mrow - mnew);
        float lloc = 0.f;
        #pragma unroll
        for (int ki = 0; ki < 16; ++ki) {
            p[ki] = __expf(p[ki] - mnew);
            lloc += p[ki];
        }
        lloc += __shfl_xor_sync(0xffffffffu, lloc, 1);
        lloc += __shfl_xor_sync(0xffffffffu, lloc, 2);
        lrow = lrow * scale + lloc;
        mrow = mnew;
        #pragma unroll
        for (int ki = 0; ki < 16; ++ki)
            Ps[(c * 16 + ki) * 64 + r] = p[ki];   // transposed store
        __syncwarp();                              // Ps shared only within 4-lane groups

        // ---- Phase B: O = O*scale + P @ V ----
        #pragma unroll
        for (int j = 0; j < 16; ++j) O[j] *= scale;
        #pragma unroll 8
        for (int k = 0; k < 64; ++k) {
            float pv = Ps[k * 64 + r];
            const float* vr = &Vs[k * PAD + c * 16];
            #pragma unroll
            for (int j4 = 0; j4 < 4; ++j4) {
                float4 v4 = *(const float4*)&vr[j4 * 4];
                O[j4 * 4 + 0] += pv * v4.x;
                O[j4 * 4 + 1] += pv * v4.y;
                O[j4 * 4 + 2] += pv * v4.z;
                O[j4 * 4 + 3] += pv * v4.w;
            }
        }
        __syncthreads();   // before next iteration overwrites Ks/Vs
    }

    float inv = 1.f / lrow;
    float* optr = g_att + ((size_t)(b * S_LEN + qg)) * EMB + h * HD + c * 16;
    #pragma unroll
    for (int j4 = 0; j4 < 4; ++j4) {
        float4 v;
        v.x = O[j4 * 4 + 0] * inv;
        v.y = O[j4 * 4 + 1] * inv;
        v.z = O[j4 * 4 + 2] * inv;
        v.w = O[j4 * 4 + 3] * inv;
        ((float4*)optr)[j4] = v;
    }
}

// ---------------------------------------------------------------------------
extern "C" void kernel_launch(void* const* d_in, const int* in_sizes, int n_in,
                              void* d_out, int out_size)
{
    const float* x  = (const float*)d_in[0];
    const float* Wq = (const float*)d_in[1];
    const float* Wk = (const float*)d_in[2];
    const float* Wv = (const float*)d_in[3];
    const float* Wp = (const float*)d_in[4];
    const float* bp = (const float*)d_in[5];
    float* out = (float*)d_out;

    float* att;
    cudaGetSymbolAddress((void**)&att, g_att);

    dim3 gqkv(EMB / TN, MTOT / TM, 3);   // (16, 64, 3)
    qkv_kernel<<<gqkv, 256>>>(x, Wq, Wk, Wv);

    int smem = (2 * 64 * PAD + 64 * 64) * (int)sizeof(float);  // 51200 B
    cudaFuncSetAttribute(attn_kernel, cudaFuncAttributeMaxDynamicSharedMemorySize, smem);
    attn_kernel<<<dim3(S_LEN / 64, NH, BATCH), 256, smem>>>();

    dim3 gp(EMB / TN, MTOT / TM);        // (16, 64)
    sgemm_kernel<<<gp, 256>>>(att, Wp, bp, out, MTOT, EMB, EMB);
}

// round 6
// speedup vs baseline: 4.1333x; 4.1333x over previous
#include <cuda_runtime.h>
#include <math.h>
#include <stdint.h>

#define S_LEN 2048
#define BATCH 2
#define EMB   1024
#define NH    16
#define HD    64
#define MTOT  (BATCH * S_LEN)   // 4096

// Scratch (no cudaMalloc allowed)
__device__ float g_q[MTOT * EMB];
__device__ float g_k[MTOT * EMB];
__device__ float g_v[MTOT * EMB];
__device__ float g_att[MTOT * EMB];

// m16n8k8 tf32 mma: A row-major (4 regs), B col-major (2 regs), C f32 (4 regs).
__device__ __forceinline__ void mma_tf32(float c[4], uint32_t a0, uint32_t a1,
                                         uint32_t a2, uint32_t a3,
                                         uint32_t b0, uint32_t b1)
{
    asm volatile(
        "mma.sync.aligned.m16n8k8.row.col.f32.tf32.tf32.f32 "
        "{%0,%1,%2,%3}, {%4,%5,%6,%7}, {%8,%9}, {%0,%1,%2,%3};"
        : "+f"(c[0]), "+f"(c[1]), "+f"(c[2]), "+f"(c[3])
        : "r"(a0), "r"(a1), "r"(a2), "r"(a3), "r"(b0), "r"(b1));
}

// Round-to-nearest tf32 (bit pattern is a valid fp32 with low 13 bits zero).
__device__ __forceinline__ uint32_t tf32_hi(float x)
{
    uint32_t r;
    asm("cvt.rna.tf32.f32 %0, %1;" : "=r"(r) : "f"(x));
    return r;
}
// Residual: x - hi(x). HW truncation of this fp32 loses only ~2^-24-level bits.
__device__ __forceinline__ uint32_t tf32_lo(float x, uint32_t hi)
{
    return __float_as_uint(x - __uint_as_float(hi));
}
__device__ __forceinline__ void split2(float x, uint32_t& hi, uint32_t& lo)
{
    hi = tf32_hi(x);
    lo = tf32_lo(x, hi);
}

// 3xTF32 compensated mma: c += A@B with A=(ah,al), B=(bh,bl).
__device__ __forceinline__ void mma3(float c[4],
    const uint32_t ah[4], const uint32_t al[4],
    uint32_t bh0, uint32_t bh1, uint32_t bl0, uint32_t bl1)
{
    mma_tf32(c, ah[0], ah[1], ah[2], ah[3], bl0, bl1);   // hi*lo
    mma_tf32(c, al[0], al[1], al[2], al[3], bh0, bh1);   // lo*hi
    mma_tf32(c, ah[0], ah[1], ah[2], ah[3], bh0, bh1);   // hi*hi (last: biggest term)
}

// ---------------------------------------------------------------------------
// 3xTF32 GEMM: C[M,N] = A[M,K] @ B[K,N] (+bias). 128x128x32 tile, 256 threads.
// 8 warps as 2(M) x 4(N); each warp 64x32 = 4 m-tiles x 4 n-tiles of m16n8k8.
// ---------------------------------------------------------------------------
#define BM 128
#define BN 128
#define BK 32
#define ASTR 36
#define BSTR 136

__device__ __forceinline__ void gemm_tf32_body(
    const float* __restrict__ A, const float* __restrict__ B,
    const float* __restrict__ bias, float* __restrict__ C,
    int M, int N, int K)
{
    __shared__ float As[BM * ASTR];
    __shared__ float Bs[BK * BSTR];

    const int tid   = threadIdx.x;
    const int lane  = tid & 31;
    const int warp  = tid >> 5;
    const int warpM = warp >> 2;          // 0..1
    const int warpN = warp & 3;           // 0..3
    const int r     = lane >> 2;          // 0..7
    const int cq    = lane & 3;           // 0..3
    const int tm0   = blockIdx.y * BM;
    const int tn0   = blockIdx.x * BN;

    float acc[4][4][4];
    #pragma unroll
    for (int mt = 0; mt < 4; ++mt)
        #pragma unroll
        for (int nt = 0; nt < 4; ++nt)
            #pragma unroll
            for (int i = 0; i < 4; ++i) acc[mt][nt][i] = 0.f;

    const int arow = tid >> 3;            // 0..31
    const int acol = (tid & 7) * 4;       // 0..28
    const int brow = tid >> 6;            // 0..3
    const int bcol = (tid & 63) * 2;      // 0..126 step 2

    for (int k0 = 0; k0 < K; k0 += BK) {
        #pragma unroll
        for (int i = 0; i < 4; ++i) {
            float4 v = *(const float4*)&A[(size_t)(tm0 + arow + i * 32) * K + k0 + acol];
            *(float4*)&As[(arow + i * 32) * ASTR + acol] = v;
        }
        #pragma unroll
        for (int i = 0; i < 8; ++i) {
            float2 v = *(const float2*)&B[(size_t)(k0 + brow + i * 4) * N + tn0 + bcol];
            *(float2*)&Bs[(brow + i * 4) * BSTR + bcol] = v;
        }
        __syncthreads();

        #pragma unroll
        for (int ks = 0; ks < 4; ++ks) {
            uint32_t ah[4][4], al[4][4];
            #pragma unroll
            for (int mt = 0; mt < 4; ++mt) {
                int row0 = warpM * 64 + mt * 16 + r;
                int kc   = ks * 8 + cq;
                split2(As[row0 * ASTR + kc],           ah[mt][0], al[mt][0]);
                split2(As[(row0 + 8) * ASTR + kc],     ah[mt][1], al[mt][1]);
                split2(As[row0 * ASTR + kc + 4],       ah[mt][2], al[mt][2]);
                split2(As[(row0 + 8) * ASTR + kc + 4], ah[mt][3], al[mt][3]);
            }
            uint32_t bh[4][2], bl[4][2];
            #pragma unroll
            for (int nt = 0; nt < 4; ++nt) {
                int ncol = warpN * 32 + nt * 8 + r;
                split2(Bs[(ks * 8 + cq) * BSTR + ncol],     bh[nt][0], bl[nt][0]);
                split2(Bs[(ks * 8 + cq + 4) * BSTR + ncol], bh[nt][1], bl[nt][1]);
            }
            #pragma unroll
            for (int mt = 0; mt < 4; ++mt)
                #pragma unroll
                for (int nt = 0; nt < 4; ++nt)
                    mma3(acc[mt][nt], ah[mt], al[mt],
                         bh[nt][0], bh[nt][1], bl[nt][0], bl[nt][1]);
        }
        __syncthreads();
    }

    #pragma unroll
    for (int mt = 0; mt < 4; ++mt) {
        int row = tm0 + warpM * 64 + mt * 16 + r;
        #pragma unroll
        for (int nt = 0; nt < 4; ++nt) {
            int col = tn0 + warpN * 32 + nt * 8 + 2 * cq;
            float b0 = 0.f, b1 = 0.f;
            if (bias) { b0 = bias[col]; b1 = bias[col + 1]; }
            float2 v0 = make_float2(acc[mt][nt][0] + b0, acc[mt][nt][1] + b1);
            float2 v1 = make_float2(acc[mt][nt][2] + b0, acc[mt][nt][3] + b1);
            *(float2*)&C[(size_t)row * N + col]       = v0;
            *(float2*)&C[(size_t)(row + 8) * N + col] = v1;
        }
    }
}

__global__ __launch_bounds__(256) void gemm_tf32_kernel(
    const float* __restrict__ A, const float* __restrict__ B,
    const float* __restrict__ bias, float* __restrict__ C,
    int M, int N, int K)
{
    gemm_tf32_body(A, B, bias, C, M, N, K);
}

__global__ __launch_bounds__(256) void qkv_tf32_kernel(
    const float* __restrict__ x,
    const float* __restrict__ Wq, const float* __restrict__ Wk,
    const float* __restrict__ Wv)
{
    const float* W;
    float* C;
    if (blockIdx.z == 0)      { W = Wq; C = g_q; }
    else if (blockIdx.z == 1) { W = Wk; C = g_k; }
    else                      { W = Wv; C = g_v; }
    gemm_tf32_body(x, W, nullptr, C, MTOT, EMB, EMB);
}

// ---------------------------------------------------------------------------
// 3xTF32 flash attention (causal). CTA = 64 queries of one (b,h), 4 warps.
// Q split fragments register-resident (scaled by 1/8). K-tiles of 64 keys.
// ---------------------------------------------------------------------------
#define KSTR 68
#define VSTR 72

__global__ __launch_bounds__(128) void attn_tf32_kernel()
{
    extern __shared__ float sm[];
    float* Ks = sm;                          // 64*KSTR
    float* Vs = sm + 64 * KSTR;              // 64*VSTR
    float* QP = sm + 64 * KSTR + 64 * VSTR;  // 64*KSTR (Q staging, then P)

    const int tid  = threadIdx.x;
    const int lane = tid & 31;
    const int warp = tid >> 5;           // 0..3
    const int r    = lane >> 2;          // 0..7
    const int cq   = lane & 3;           // 0..3
    const int bq   = gridDim.x - 1 - blockIdx.x;  // heavy blocks first
    const int h    = blockIdx.y;
    const int b    = blockIdx.z;
    const int qbase = bq * 64;

    const int lrow = tid >> 4;           // 0..7
    const int lcol = (tid & 15) * 4;     // 0..60

    #pragma unroll
    for (int i = 0; i < 8; ++i) {
        int row = lrow + i * 8;
        *(float4*)&QP[row * KSTR + lcol] =
            *(const float4*)&g_q[((size_t)(b * S_LEN + qbase + row)) * EMB + h * HD + lcol];
    }
    __syncthreads();

    uint32_t qh[8][4], ql[8][4];
    {
        int row0 = warp * 16 + r;
        #pragma unroll
        for (int ks = 0; ks < 8; ++ks) {
            int kc = ks * 8 + cq;
            split2(QP[row0 * KSTR + kc] * 0.125f,           qh[ks][0], ql[ks][0]);
            split2(QP[(row0 + 8) * KSTR + kc] * 0.125f,     qh[ks][1], ql[ks][1]);
            split2(QP[row0 * KSTR + kc + 4] * 0.125f,       qh[ks][2], ql[ks][2]);
            split2(QP[(row0 + 8) * KSTR + kc + 4] * 0.125f, qh[ks][3], ql[ks][3]);
        }
    }
    __syncthreads();   // QP now free for P

    float o[8][4];
    #pragma unroll
    for (int nt = 0; nt < 8; ++nt)
        #pragma unroll
        for (int i = 0; i < 4; ++i) o[nt][i] = 0.f;
    float m0 = -1e30f, m1 = -1e30f, l0 = 0.f, l1 = 0.f;

    const int qr0 = warp * 16 + r;
    const int qr1 = qr0 + 8;

    for (int kb = 0; kb <= bq; ++kb) {
        #pragma unroll
        for (int i = 0; i < 8; ++i) {
            int row = lrow + i * 8;
            size_t g = ((size_t)(b * S_LEN + kb * 64 + row)) * EMB + h * HD + lcol;
            *(float4*)&Ks[row * KSTR + lcol] = *(const float4*)&g_k[g];
            *(float4*)&Vs[row * VSTR + lcol] = *(const float4*)&g_v[g];
        }
        __syncthreads();

        // S = (Q/8) @ K^T   (3xTF32)
        float s[8][4];
        #pragma unroll
        for (int nt = 0; nt < 8; ++nt)
            #pragma unroll
            for (int i = 0; i < 4; ++i) s[nt][i] = 0.f;
        #pragma unroll
        for (int ks = 0; ks < 8; ++ks) {
            int kc = ks * 8 + cq;
            #pragma unroll
            for (int nt = 0; nt < 8; ++nt) {
                int krow = nt * 8 + r;
                uint32_t kh0, kl0, kh1, kl1;
                split2(Ks[krow * KSTR + kc],     kh0, kl0);
                split2(Ks[krow * KSTR + kc + 4], kh1, kl1);
                mma3(s[nt], qh[ks], ql[ks], kh0, kh1, kl0, kl1);
            }
        }

        if (kb == bq) {
            #pragma unroll
            for (int nt = 0; nt < 8; ++nt) {
                int kc = nt * 8 + 2 * cq;
                if (kc     > qr0) s[nt][0] = -1e30f;
                if (kc + 1 > qr0) s[nt][1] = -1e30f;
                if (kc     > qr1) s[nt][2] = -1e30f;
                if (kc + 1 > qr1) s[nt][3] = -1e30f;
            }
        }

        float mx0 = -1e30f, mx1 = -1e30f;
        #pragma unroll
        for (int nt = 0; nt < 8; ++nt) {
            mx0 = fmaxf(mx0, fmaxf(s[nt][0], s[nt][1]));
            mx1 = fmaxf(mx1, fmaxf(s[nt][2], s[nt][3]));
        }
        mx0 = fmaxf(mx0, __shfl_xor_sync(0xffffffffu, mx0, 1));
        mx0 = fmaxf(mx0, __shfl_xor_sync(0xffffffffu, mx0, 2));
        mx1 = fmaxf(mx1, __shfl_xor_sync(0xffffffffu, mx1, 1));
        mx1 = fmaxf(mx1, __shfl_xor_sync(0xffffffffu, mx1, 2));
        float mn0 = fmaxf(m0, mx0), mn1 = fmaxf(m1, mx1);
        float sc0 = __expf(m0 - mn0), sc1 = __expf(m1 - mn1);
        m0 = mn0; m1 = mn1;
        float ls0 = 0.f, ls1 = 0.f;
        #pragma unroll
        for (int nt = 0; nt < 8; ++nt) {
            s[nt][0] = __expf(s[nt][0] - m0);
            s[nt][1] = __expf(s[nt][1] - m0);
            s[nt][2] = __expf(s[nt][2] - m1);
            s[nt][3] = __expf(s[nt][3] - m1);
            ls0 += s[nt][0] + s[nt][1];
            ls1 += s[nt][2] + s[nt][3];
        }
        ls0 += __shfl_xor_sync(0xffffffffu, ls0, 1);
        ls0 += __shfl_xor_sync(0xffffffffu, ls0, 2);
        ls1 += __shfl_xor_sync(0xffffffffu, ls1, 1);
        ls1 += __shfl_xor_sync(0xffffffffu, ls1, 2);
        l0 = l0 * sc0 + ls0;
        l1 = l1 * sc1 + ls1;
        #pragma unroll
        for (int nt = 0; nt < 8; ++nt) {
            o[nt][0] *= sc0; o[nt][1] *= sc0;
            o[nt][2] *= sc1; o[nt][3] *= sc1;
        }

        // P -> smem (per-warp private rows)
        #pragma unroll
        for (int nt = 0; nt < 8; ++nt) {
            int kc = nt * 8 + 2 * cq;
            QP[qr0 * KSTR + kc]     = s[nt][0];
            QP[qr0 * KSTR + kc + 1] = s[nt][1];
            QP[qr1 * KSTR + kc]     = s[nt][2];
            QP[qr1 * KSTR + kc + 1] = s[nt][3];
        }
        __syncwarp();

        // O += P @ V   (3xTF32)
        #pragma unroll
        for (int kv = 0; kv < 8; ++kv) {
            int kc = kv * 8 + cq;
            uint32_t ph[4], pl[4];
            split2(QP[qr0 * KSTR + kc],     ph[0], pl[0]);
            split2(QP[qr1 * KSTR + kc],     ph[1], pl[1]);
            split2(QP[qr0 * KSTR + kc + 4], ph[2], pl[2]);
            split2(QP[qr1 * KSTR + kc + 4], ph[3], pl[3]);
            #pragma unroll
            for (int nt = 0; nt < 8; ++nt) {
                int ncol = nt * 8 + r;
                uint32_t vh0, vl0, vh1, vl1;
                split2(Vs[(kv * 8 + cq) * VSTR + ncol],     vh0, vl0);
                split2(Vs[(kv * 8 + cq + 4) * VSTR + ncol], vh1, vl1);
                mma3(o[nt], ph, pl, vh0, vh1, vl0, vl1);
            }
        }
        __syncthreads();
    }

    float inv0 = 1.f / l0, inv1 = 1.f / l1;
    #pragma unroll
    for (int nt = 0; nt < 8; ++nt) {
        int col = h * HD + nt * 8 + 2 * cq;
        float2 v0 = make_float2(o[nt][0] * inv0, o[nt][1] * inv0);
        float2 v1 = make_float2(o[nt][2] * inv1, o[nt][3] * inv1);
        *(float2*)&g_att[((size_t)(b * S_LEN + qbase + qr0)) * EMB + col] = v0;
        *(float2*)&g_att[((size_t)(b * S_LEN + qbase + qr1)) * EMB + col] = v1;
    }
}

// ---------------------------------------------------------------------------
extern "C" void kernel_launch(void* const* d_in, const int* in_sizes, int n_in,
                              void* d_out, int out_size)
{
    const float* x  = (const float*)d_in[0];
    const float* Wq = (const float*)d_in[1];
    const float* Wk = (const float*)d_in[2];
    const float* Wv = (const float*)d_in[3];
    const float* Wp = (const float*)d_in[4];
    const float* bp = (const float*)d_in[5];
    float* out = (float*)d_out;

    float* att;
    cudaGetSymbolAddress((void**)&att, g_att);

    dim3 gqkv(EMB / BN, MTOT / BM, 3);   // (8, 32, 3)
    qkv_tf32_kernel<<<gqkv, 256>>>(x, Wq, Wk, Wv);

    int smem = (64 * KSTR + 64 * VSTR + 64 * KSTR) * (int)sizeof(float);  // 53248
    cudaFuncSetAttribute(attn_tf32_kernel, cudaFuncAttributeMaxDynamicSharedMemorySize, smem);
    attn_tf32_kernel<<<dim3(S_LEN / 64, NH, BATCH), 128, smem>>>();

    dim3 gp(EMB / BN, MTOT / BM);        // (8, 32)
    gemm_tf32_kernel<<<gp, 256>>>(att, Wp, bp, out, MTOT, EMB, EMB);
}

// round 7
// speedup vs baseline: 5.0986x; 1.2335x over previous
#include <cuda_runtime.h>
#include <math.h>
#include <stdint.h>

#define S_LEN 2048
#define BATCH 2
#define EMB   1024
#define NH    16
#define HD    64
#define MTOT  (BATCH * S_LEN)   // 4096

__device__ float g_q[MTOT * EMB];
__device__ float g_k[MTOT * EMB];
__device__ float g_v[MTOT * EMB];
__device__ float g_att[MTOT * EMB];

// m16n8k8 tf32 mma: A row-major (4 regs), B col-major (2 regs), C f32 (4 regs).
__device__ __forceinline__ void mma_tf32(float c[4], uint32_t a0, uint32_t a1,
                                         uint32_t a2, uint32_t a3,
                                         uint32_t b0, uint32_t b1)
{
    asm volatile(
        "mma.sync.aligned.m16n8k8.row.col.f32.tf32.tf32.f32 "
        "{%0,%1,%2,%3}, {%4,%5,%6,%7}, {%8,%9}, {%0,%1,%2,%3};"
        : "+f"(c[0]), "+f"(c[1]), "+f"(c[2]), "+f"(c[3])
        : "r"(a0), "r"(a1), "r"(a2), "r"(a3), "r"(b0), "r"(b1));
}

__device__ __forceinline__ uint32_t tf32_rna(float x)
{
    uint32_t r;
    asm("cvt.rna.tf32.f32 %0, %1;" : "=r"(r) : "f"(x));
    return r;
}
__device__ __forceinline__ void split2(float x, float& hi, float& lo)
{
    hi = __uint_as_float(tf32_rna(x));
    lo = x - hi;
}
__device__ __forceinline__ uint32_t f2b(float x) { return __float_as_uint(x); }

// cp.async 16B
__device__ __forceinline__ void cp16(void* smem, const void* gmem)
{
    uint32_t s = (uint32_t)__cvta_generic_to_shared(smem);
    asm volatile("cp.async.cg.shared.global [%0], [%1], 16;" :: "r"(s), "l"(gmem));
}
#define CP_COMMIT() asm volatile("cp.async.commit_group;" ::: "memory")
#define CP_WAIT1()  asm volatile("cp.async.wait_group 1;" ::: "memory")

// ---------------------------------------------------------------------------
// 3xTF32 GEMM, hi/lo pre-split in smem + register double buffering.
// 128x128x32 tile, 256 threads, 8 warps as 2(M) x 4(N).
// ---------------------------------------------------------------------------
#define BM 128
#define BN 128
#define BK 32
#define ASTR 36
#define BSTR 136
#define GEMM_SMEM ((2 * BM * ASTR + 2 * BK * BSTR) * 4)   // 71680 B

__device__ __forceinline__ void gemm_tf32_body(
    const float* __restrict__ A, const float* __restrict__ B,
    const float* __restrict__ bias, float* __restrict__ C,
    int M, int N, int K)
{
    extern __shared__ float dsm[];
    float* Ah = dsm;                       // BM*ASTR
    float* Al = Ah + BM * ASTR;
    float* Bh = Al + BM * ASTR;            // BK*BSTR
    float* Bl = Bh + BK * BSTR;

    const int tid   = threadIdx.x;
    const int lane  = tid & 31;
    const int warp  = tid >> 5;
    const int warpM = warp >> 2;
    const int warpN = warp & 3;
    const int r     = lane >> 2;
    const int cq    = lane & 3;
    const int tm0   = blockIdx.y * BM;
    const int tn0   = blockIdx.x * BN;

    float acc[4][4][4];
    #pragma unroll
    for (int mt = 0; mt < 4; ++mt)
        #pragma unroll
        for (int nt = 0; nt < 4; ++nt)
            #pragma unroll
            for (int i = 0; i < 4; ++i) acc[mt][nt][i] = 0.f;

    const int arow = tid >> 3;            // 0..31
    const int acol = (tid & 7) * 4;       // 0..28
    const int brow = tid >> 6;            // 0..3
    const int bcol = (tid & 63) * 2;      // 0..126

    float4 a4[4];
    float2 b2[8];

    // Prologue: load tile 0
    #pragma unroll
    for (int i = 0; i < 4; ++i)
        a4[i] = *(const float4*)&A[(size_t)(tm0 + arow + i * 32) * K + acol];
    #pragma unroll
    for (int i = 0; i < 8; ++i)
        b2[i] = *(const float2*)&B[(size_t)(brow + i * 4) * N + tn0 + bcol];

    for (int k0 = 0; k0 < K; k0 += BK) {
        // Split + store current registers to smem
        #pragma unroll
        for (int i = 0; i < 4; ++i) {
            int row = arow + i * 32;
            float4 h, l;
            split2(a4[i].x, h.x, l.x); split2(a4[i].y, h.y, l.y);
            split2(a4[i].z, h.z, l.z); split2(a4[i].w, h.w, l.w);
            *(float4*)&Ah[row * ASTR + acol] = h;
            *(float4*)&Al[row * ASTR + acol] = l;
        }
        #pragma unroll
        for (int i = 0; i < 8; ++i) {
            int row = brow + i * 4;
            float2 h, l;
            split2(b2[i].x, h.x, l.x); split2(b2[i].y, h.y, l.y);
            *(float2*)&Bh[row * BSTR + bcol] = h;
            *(float2*)&Bl[row * BSTR + bcol] = l;
        }
        __syncthreads();

        // Prefetch next tile into registers (overlaps with MMA below)
        int kn = k0 + BK;
        if (kn < K) {
            #pragma unroll
            for (int i = 0; i < 4; ++i)
                a4[i] = *(const float4*)&A[(size_t)(tm0 + arow + i * 32) * K + kn + acol];
            #pragma unroll
            for (int i = 0; i < 8; ++i)
                b2[i] = *(const float2*)&B[(size_t)(kn + brow + i * 4) * N + tn0 + bcol];
        }

        #pragma unroll
        for (int ks = 0; ks < 4; ++ks) {
            uint32_t ah[4][4], al[4][4];
            #pragma unroll
            for (int mt = 0; mt < 4; ++mt) {
                int row0 = warpM * 64 + mt * 16 + r;
                int kc   = ks * 8 + cq;
                ah[mt][0] = f2b(Ah[row0 * ASTR + kc]);
                ah[mt][1] = f2b(Ah[(row0 + 8) * ASTR + kc]);
                ah[mt][2] = f2b(Ah[row0 * ASTR + kc + 4]);
                ah[mt][3] = f2b(Ah[(row0 + 8) * ASTR + kc + 4]);
                al[mt][0] = f2b(Al[row0 * ASTR + kc]);
                al[mt][1] = f2b(Al[(row0 + 8) * ASTR + kc]);
                al[mt][2] = f2b(Al[row0 * ASTR + kc + 4]);
                al[mt][3] = f2b(Al[(row0 + 8) * ASTR + kc + 4]);
            }
            #pragma unroll
            for (int nt = 0; nt < 4; ++nt) {
                int ncol = warpN * 32 + nt * 8 + r;
                uint32_t bh0 = f2b(Bh[(ks * 8 + cq) * BSTR + ncol]);
                uint32_t bh1 = f2b(Bh[(ks * 8 + cq + 4) * BSTR + ncol]);
                uint32_t bl0 = f2b(Bl[(ks * 8 + cq) * BSTR + ncol]);
                uint32_t bl1 = f2b(Bl[(ks * 8 + cq + 4) * BSTR + ncol]);
                #pragma unroll
                for (int mt = 0; mt < 4; ++mt) {
                    mma_tf32(acc[mt][nt], ah[mt][0], ah[mt][1], ah[mt][2], ah[mt][3], bl0, bl1);
                    mma_tf32(acc[mt][nt], al[mt][0], al[mt][1], al[mt][2], al[mt][3], bh0, bh1);
                    mma_tf32(acc[mt][nt], ah[mt][0], ah[mt][1], ah[mt][2], ah[mt][3], bh0, bh1);
                }
            }
        }
        __syncthreads();
    }

    #pragma unroll
    for (int mt = 0; mt < 4; ++mt) {
        int row = tm0 + warpM * 64 + mt * 16 + r;
        #pragma unroll
        for (int nt = 0; nt < 4; ++nt) {
            int col = tn0 + warpN * 32 + nt * 8 + 2 * cq;
            float b0 = 0.f, b1 = 0.f;
            if (bias) { b0 = bias[col]; b1 = bias[col + 1]; }
            float2 v0 = make_float2(acc[mt][nt][0] + b0, acc[mt][nt][1] + b1);
            float2 v1 = make_float2(acc[mt][nt][2] + b0, acc[mt][nt][3] + b1);
            *(float2*)&C[(size_t)row * N + col]       = v0;
            *(float2*)&C[(size_t)(row + 8) * N + col] = v1;
        }
    }
}

__global__ __launch_bounds__(256) void gemm_tf32_kernel(
    const float* __restrict__ A, const float* __restrict__ B,
    const float* __restrict__ bias, float* __restrict__ C,
    int M, int N, int K)
{
    gemm_tf32_body(A, B, bias, C, M, N, K);
}

__global__ __launch_bounds__(256) void qkv_tf32_kernel(
    const float* __restrict__ x,
    const float* __restrict__ Wq, const float* __restrict__ Wk,
    const float* __restrict__ Wv)
{
    const float* W;
    float* C;
    if (blockIdx.z == 0)      { W = Wq; C = g_q; }
    else if (blockIdx.z == 1) { W = Wk; C = g_k; }
    else                      { W = Wv; C = g_v; }
    gemm_tf32_body(x, W, nullptr, C, MTOT, EMB, EMB);
}

// ---------------------------------------------------------------------------
// 1xTF32 (rna-rounded) flash attention, cp.async double-buffered K/V tiles.
// CTA = 64 queries of one (b,h), 4 warps.
// ---------------------------------------------------------------------------
#define KSTR 68
#define VSTR 72
#define KSZ (64 * KSTR)
#define VSZ (64 * VSTR)
#define ATTN_SMEM ((2 * (KSZ + VSZ) + KSZ) * 4)   // 89088 B

__global__ __launch_bounds__(128) void attn_tf32_kernel()
{
    extern __shared__ float sm[];
    float* Ks[2] = { sm,            sm + KSZ + VSZ };
    float* Vs[2] = { sm + KSZ,      sm + 2 * KSZ + VSZ };
    float* QP    = sm + 2 * (KSZ + VSZ);

    const int tid  = threadIdx.x;
    const int lane = tid & 31;
    const int warp = tid >> 5;
    const int r    = lane >> 2;
    const int cq   = lane & 3;
    const int bq   = gridDim.x - 1 - blockIdx.x;
    const int h    = blockIdx.y;
    const int b    = blockIdx.z;
    const int qbase = bq * 64;

    const int lrow = tid >> 4;           // 0..7
    const int lcol = (tid & 15) * 4;     // 0..60

    // Issue tile 0 K/V loads immediately
    {
        #pragma unroll
        for (int i = 0; i < 8; ++i) {
            int row = lrow + i * 8;
            size_t g = ((size_t)(b * S_LEN + row)) * EMB + h * HD + lcol;
            cp16(&Ks[0][row * KSTR + lcol], &g_k[g]);
            cp16(&Vs[0][row * VSTR + lcol], &g_v[g]);
        }
        CP_COMMIT();
    }

    // Stage Q, build rna-rounded fragments (scaled by 1/8)
    #pragma unroll
    for (int i = 0; i < 8; ++i) {
        int row = lrow + i * 8;
        *(float4*)&QP[row * KSTR + lcol] =
            *(const float4*)&g_q[((size_t)(b * S_LEN + qbase + row)) * EMB + h * HD + lcol];
    }
    __syncthreads();

    uint32_t qf[8][4];
    {
        int row0 = warp * 16 + r;
        #pragma unroll
        for (int ks = 0; ks < 8; ++ks) {
            int kc = ks * 8 + cq;
            qf[ks][0] = tf32_rna(QP[row0 * KSTR + kc] * 0.125f);
            qf[ks][1] = tf32_rna(QP[(row0 + 8) * KSTR + kc] * 0.125f);
            qf[ks][2] = tf32_rna(QP[row0 * KSTR + kc + 4] * 0.125f);
            qf[ks][3] = tf32_rna(QP[(row0 + 8) * KSTR + kc + 4] * 0.125f);
        }
    }
    __syncthreads();   // QP now free for P

    float o[8][4];
    #pragma unroll
    for (int nt = 0; nt < 8; ++nt)
        #pragma unroll
        for (int i = 0; i < 4; ++i) o[nt][i] = 0.f;
    float m0 = -1e30f, m1 = -1e30f, l0 = 0.f, l1 = 0.f;

    const int qr0 = warp * 16 + r;
    const int qr1 = qr0 + 8;

    for (int kb = 0; kb <= bq; ++kb) {
        const int cur = kb & 1;
        // Issue next tile into the other stage (its compute finished last iter)
        if (kb < bq) {
            float* Kn = Ks[cur ^ 1];
            float* Vn = Vs[cur ^ 1];
            #pragma unroll
            for (int i = 0; i < 8; ++i) {
                int row = lrow + i * 8;
                size_t g = ((size_t)(b * S_LEN + (kb + 1) * 64 + row)) * EMB + h * HD + lcol;
                cp16(&Kn[row * KSTR + lcol], &g_k[g]);
                cp16(&Vn[row * VSTR + lcol], &g_v[g]);
            }
        }
        CP_COMMIT();
        CP_WAIT1();          // current tile resident
        __syncthreads();

        const float* Kc = Ks[cur];
        const float* Vc = Vs[cur];

        // S = (Q/8) @ K^T  (1xTF32, rna)
        float s[8][4];
        #pragma unroll
        for (int nt = 0; nt < 8; ++nt)
            #pragma unroll
            for (int i = 0; i < 4; ++i) s[nt][i] = 0.f;
        #pragma unroll
        for (int ks = 0; ks < 8; ++ks) {
            int kc = ks * 8 + cq;
            #pragma unroll
            for (int nt = 0; nt < 8; ++nt) {
                int krow = nt * 8 + r;
                uint32_t b0 = tf32_rna(Kc[krow * KSTR + kc]);
                uint32_t b1 = tf32_rna(Kc[krow * KSTR + kc + 4]);
                mma_tf32(s[nt], qf[ks][0], qf[ks][1], qf[ks][2], qf[ks][3], b0, b1);
            }
        }

        if (kb == bq) {
            #pragma unroll
            for (int nt = 0; nt < 8; ++nt) {
                int kc = nt * 8 + 2 * cq;
                if (kc     > qr0) s[nt][0] = -1e30f;
                if (kc + 1 > qr0) s[nt][1] = -1e30f;
                if (kc     > qr1) s[nt][2] = -1e30f;
                if (kc + 1 > qr1) s[nt][3] = -1e30f;
            }
        }

        float mx0 = -1e30f, mx1 = -1e30f;
        #pragma unroll
        for (int nt = 0; nt < 8; ++nt) {
            mx0 = fmaxf(mx0, fmaxf(s[nt][0], s[nt][1]));
            mx1 = fmaxf(mx1, fmaxf(s[nt][2], s[nt][3]));
        }
        mx0 = fmaxf(mx0, __shfl_xor_sync(0xffffffffu, mx0, 1));
        mx0 = fmaxf(mx0, __shfl_xor_sync(0xffffffffu, mx0, 2));
        mx1 = fmaxf(mx1, __shfl_xor_sync(0xffffffffu, mx1, 1));
        mx1 = fmaxf(mx1, __shfl_xor_sync(0xffffffffu, mx1, 2));
        float mn0 = fmaxf(m0, mx0), mn1 = fmaxf(m1, mx1);
        float sc0 = __expf(m0 - mn0), sc1 = __expf(m1 - mn1);
        m0 = mn0; m1 = mn1;
        float ls0 = 0.f, ls1 = 0.f;
        #pragma unroll
        for (int nt = 0; nt < 8; ++nt) {
            s[nt][0] = __expf(s[nt][0] - m0);
            s[nt][1] = __expf(s[nt][1] - m0);
            s[nt][2] = __expf(s[nt][2] - m1);
            s[nt][3] = __expf(s[nt][3] - m1);
            ls0 += s[nt][0] + s[nt][1];
            ls1 += s[nt][2] + s[nt][3];
        }
        ls0 += __shfl_xor_sync(0xffffffffu, ls0, 1);
        ls0 += __shfl_xor_sync(0xffffffffu, ls0, 2);
        ls1 += __shfl_xor_sync(0xffffffffu, ls1, 1);
        ls1 += __shfl_xor_sync(0xffffffffu, ls1, 2);
        l0 = l0 * sc0 + ls0;
        l1 = l1 * sc1 + ls1;
        #pragma unroll
        for (int nt = 0; nt < 8; ++nt) {
            o[nt][0] *= sc0; o[nt][1] *= sc0;
            o[nt][2] *= sc1; o[nt][3] *= sc1;
        }

        // P -> smem (per-warp private rows)
        #pragma unroll
        for (int nt = 0; nt < 8; ++nt) {
            int kc = nt * 8 + 2 * cq;
            QP[qr0 * KSTR + kc]     = s[nt][0];
            QP[qr0 * KSTR + kc + 1] = s[nt][1];
            QP[qr1 * KSTR + kc]     = s[nt][2];
            QP[qr1 * KSTR + kc + 1] = s[nt][3];
        }
        __syncwarp();

        // O += P @ V  (1xTF32, rna)
        #pragma unroll
        for (int kv = 0; kv < 8; ++kv) {
            int kc = kv * 8 + cq;
            uint32_t p0 = tf32_rna(QP[qr0 * KSTR + kc]);
            uint32_t p1 = tf32_rna(QP[qr1 * KSTR + kc]);
            uint32_t p2 = tf32_rna(QP[qr0 * KSTR + kc + 4]);
            uint32_t p3 = tf32_rna(QP[qr1 * KSTR + kc + 4]);
            #pragma unroll
            for (int nt = 0; nt < 8; ++nt) {
                int ncol = nt * 8 + r;
                uint32_t b0 = tf32_rna(Vc[(kv * 8 + cq) * VSTR + ncol]);
                uint32_t b1 = tf32_rna(Vc[(kv * 8 + cq + 4) * VSTR + ncol]);
                mma_tf32(o[nt], p0, p1, p2, p3, b0, b1);
            }
        }
        __syncthreads();   // compute done; stage may be re-filled next iter
    }

    float inv0 = 1.f / l0, inv1 = 1.f / l1;
    #pragma unroll
    for (int nt = 0; nt < 8; ++nt) {
        int col = h * HD + nt * 8 + 2 * cq;
        float2 v0 = make_float2(o[nt][0] * inv0, o[nt][1] * inv0);
        float2 v1 = make_float2(o[nt][2] * inv1, o[nt][3] * inv1);
        *(float2*)&g_att[((size_t)(b * S_LEN + qbase + qr0)) * EMB + col] = v0;
        *(float2*)&g_att[((size_t)(b * S_LEN + qbase + qr1)) * EMB + col] = v1;
    }
}

// ---------------------------------------------------------------------------
extern "C" void kernel_launch(void* const* d_in, const int* in_sizes, int n_in,
                              void* d_out, int out_size)
{
    const float* x  = (const float*)d_in[0];
    const float* Wq = (const float*)d_in[1];
    const float* Wk = (const float*)d_in[2];
    const float* Wv = (const float*)d_in[3];
    const float* Wp = (const float*)d_in[4];
    const float* bp = (const float*)d_in[5];
    float* out = (float*)d_out;

    float* att;
    cudaGetSymbolAddress((void**)&att, g_att);

    cudaFuncSetAttribute(qkv_tf32_kernel,  cudaFuncAttributeMaxDynamicSharedMemorySize, GEMM_SMEM);
    cudaFuncSetAttribute(gemm_tf32_kernel, cudaFuncAttributeMaxDynamicSharedMemorySize, GEMM_SMEM);
    cudaFuncSetAttribute(attn_tf32_kernel, cudaFuncAttributeMaxDynamicSharedMemorySize, ATTN_SMEM);

    dim3 gqkv(EMB / BN, MTOT / BM, 3);   // (8, 32, 3)
    qkv_tf32_kernel<<<gqkv, 256, GEMM_SMEM>>>(x, Wq, Wk, Wv);

    attn_tf32_kernel<<<dim3(S_LEN / 64, NH, BATCH), 128, ATTN_SMEM>>>();

    dim3 gp(EMB / BN, MTOT / BM);        // (8, 32)
    gemm_tf32_kernel<<<gp, 256, GEMM_SMEM>>>(att, Wp, bp, out, MTOT, EMB, EMB);
}